// round 9
// baseline (speedup 1.0000x reference)
#include <cuda_runtime.h>
#include <cstdint>
#include <cstddef>

#define BS 256
#define KDIM 1024
#define NDIM 1024
#define NSTATES 20
#define TN 32
#define RCH 16
#define NWARPS 8
#define KSL 128        // k per warp
#define KST 8          // k per stage
#define NSTG (KSL / KST)   // 16
#define RING 3
#define NTHREADS 256
#define MAXE 36
#define XS_FLOATS (KDIM * RCH)          // 64KB
#define WSTG 512                        // floats per warp-stage (mask 256 + kern 256)
#define SMEM_BYTES ((XS_FLOATS + NWARPS * RING * WSTG) * 4)   // 114688

__device__ int g_rows[MAXE][RCH];
__device__ int g_nrows[MAXE];
__device__ int g_state[MAXE];
__device__ int g_nentries;

__device__ __forceinline__ unsigned long long fma2(unsigned long long a, unsigned long long b, unsigned long long c) {
    unsigned long long d;
    asm("fma.rn.f32x2 %0, %1, %2, %3;" : "=l"(d) : "l"(a), "l"(b), "l"(c));
    return d;
}
__device__ __forceinline__ unsigned long long dup2(float v) {
    unsigned long long d; unsigned u = __float_as_uint(v);
    asm("mov.b64 %0, {%1, %1};" : "=l"(d) : "r"(u));
    return d;
}
__device__ __forceinline__ uint32_t s2u(const void* p) {
    uint32_t a;
    asm("{ .reg .u64 t; cvta.to.shared.u64 t, %1; cvt.u32.u64 %0, t; }" : "=r"(a) : "l"(p));
    return a;
}
#define CP16(dst, src) asm volatile("cp.async.cg.shared.global [%0], [%1], 16;" :: "r"(dst), "l"(src))
#define CPCOMMIT() asm volatile("cp.async.commit_group;" ::: "memory")
#define CPWAIT2()  asm volatile("cp.async.wait_group 2;" ::: "memory")

// ---- kernel A: build compact work entries ----
__global__ void build_entries_kernel(const int* __restrict__ state)
{
    __shared__ int cnt[NWARPS][NSTATES];
    __shared__ int ebase[NSTATES];
    __shared__ int stot[NSTATES];
    const int t = threadIdx.x, w = t >> 5, lane = t & 31;
    if (t < NWARPS * NSTATES) ((int*)cnt)[t] = 0;
    __syncthreads();
    const int s = state[t];
    const unsigned grp = __match_any_sync(0xffffffffu, s);
    const int lr = __popc(grp & ((1u << lane) - 1u));
    if (lr == 0) cnt[w][s] = __popc(grp);
    __syncthreads();
    if (t < NSTATES) {
        int tot = 0;
#pragma unroll
        for (int ww = 0; ww < NWARPS; ww++) tot += cnt[ww][t];
        stot[t] = tot;
    }
    __syncthreads();
    if (t == 0) {
        int b = 0;
        for (int i = 0; i < NSTATES; i++) { ebase[i] = b; b += (stot[i] + RCH - 1) / RCH; }
        g_nentries = b;
    }
    __syncthreads();
    int before = 0;
    for (int w2 = 0; w2 < w; w2++) before += cnt[w2][s];
    const int rank = before + lr;
    g_rows[ebase[s] + (rank >> 4)][rank & 15] = t;
    if (t < NSTATES) {
        const int nch = (stot[t] + RCH - 1) / RCH;
        for (int c = 0; c < nch; c++) {
            g_nrows[ebase[t] + c] = min(stot[t] - c * RCH, RCH);
            g_state[ebase[t] + c] = t;
        }
    }
}

// ---- kernel B: one (entry, 32-col n-tile) per block ----
__global__ __launch_bounds__(NTHREADS, 2)
void masked_dense_kernel(const float* __restrict__ x,
                         const float* __restrict__ kern,
                         const float* __restrict__ masks,
                         float* __restrict__ out)
{
    extern __shared__ float xs[];        // [0,64KB): x transposed [k][16]; then ring
    __shared__ int rowlist[RCH];
    __shared__ int meta[2];

    const int e = blockIdx.y;
    if (e >= g_nentries) return;         // uniform exit before any sync

    const int t = threadIdx.x, w = t >> 5, lane = t & 31;
    const int n0 = blockIdx.x * TN;
    if (t < RCH) rowlist[t] = g_rows[e][t];
    if (t == 16) meta[0] = g_nrows[e];
    if (t == 17) meta[1] = g_state[e];
    __syncthreads();
    const int nrows = meta[0], s = meta[1];

    // stage ALL of x transposed once: xs[k*16 + r]
    for (int e4 = t; e4 < RCH * (KDIM / 4); e4 += NTHREADS) {
        const int r = e4 & 15, kq = e4 >> 4;
        float4 v = (r < nrows) ? *(const float4*)&x[(size_t)rowlist[r] * KDIM + kq * 4]
                               : make_float4(0.f, 0.f, 0.f, 0.f);
        xs[(kq * 4 + 0) * 16 + r] = v.x;
        xs[(kq * 4 + 1) * 16 + r] = v.y;
        xs[(kq * 4 + 2) * 16 + r] = v.z;
        xs[(kq * 4 + 3) * 16 + r] = v.w;
    }
    __syncthreads();

    // warp-private cp.async ring: mask/kern for k in [w*KSL, w*KSL+KSL)
    float* ringp = xs + XS_FLOATS + w * RING * WSTG;     // read view
    const uint32_t ring0 = s2u(ringp);                   // write view (shared addr)
    const int kw0 = w * KSL;
    const float* mbase = masks + (size_t)s * KDIM * NDIM + n0;
    const float* kbase = kern + n0;

    // lane copy map: per array per stage, 2 x 16B: idx = p*32+lane -> kr=idx>>3, nq=(idx&7)*4
    const int kr0 = lane >> 3, kr1 = (32 + lane) >> 3;
    const int nq0 = (lane & 7) * 4;
    const uint32_t d0 = ring0 + (uint32_t)(kr0 * 32 + nq0) * 4;
    const uint32_t d1 = ring0 + (uint32_t)(kr1 * 32 + nq0) * 4;

#define ISSUE(j, slot) do { \
    const int kg_ = kw0 + (j) * KST; \
    const uint32_t sb_ = (uint32_t)(slot) * (WSTG * 4); \
    CP16(d0 + sb_,        mbase + (size_t)(kg_ + kr0) * NDIM + nq0); \
    CP16(d0 + sb_ + 1024, kbase + (size_t)(kg_ + kr0) * NDIM + nq0); \
    CP16(d1 + sb_,        mbase + (size_t)(kg_ + kr1) * NDIM + nq0); \
    CP16(d1 + sb_ + 1024, kbase + (size_t)(kg_ + kr1) * NDIM + nq0); \
} while (0)

#pragma unroll
    for (int j = 0; j < RING; j++) { ISSUE(j, j); CPCOMMIT(); }

    unsigned long long acc[8];
#pragma unroll
    for (int j = 0; j < 8; j++) acc[j] = 0ull;
    const float* xk = xs + kw0 * 16;

    for (int j = 0; j < NSTG; j++) {
        CPWAIT2();
        __syncwarp();
        const int slot = j % RING;
        const float* mr = ringp + slot * WSTG;
#pragma unroll
        for (int kr = 0; kr < KST; kr++) {
            const float wv = mr[kr * 32 + lane] * mr[256 + kr * 32 + lane];
            const unsigned long long wp = dup2(wv);
            const ulonglong2* xp = (const ulonglong2*)(xk + (j * KST + kr) * 16);
            const ulonglong2 a0 = xp[0], a1 = xp[1], a2 = xp[2], a3 = xp[3];
            acc[0] = fma2(a0.x, wp, acc[0]);
            acc[1] = fma2(a0.y, wp, acc[1]);
            acc[2] = fma2(a1.x, wp, acc[2]);
            acc[3] = fma2(a1.y, wp, acc[3]);
            acc[4] = fma2(a2.x, wp, acc[4]);
            acc[5] = fma2(a2.y, wp, acc[5]);
            acc[6] = fma2(a3.x, wp, acc[6]);
            acc[7] = fma2(a3.y, wp, acc[7]);
        }
        if (j + RING < NSTG) ISSUE(j + RING, slot);
        CPCOMMIT();                                   // commit every iter (may be empty)
    }
#undef ISSUE

    __syncthreads();   // all warps done with ring before overlay

    // cross-warp reduction overlay on ring region (16KB of 48KB)
    unsigned long long* red = (unsigned long long*)(xs + XS_FLOATS);
#pragma unroll
    for (int j = 0; j < 8; j++) red[(w * 8 + j) * 32 + lane] = acc[j];
    __syncthreads();

    const float* redf = (const float*)(xs + XS_FLOATS);
    for (int e2 = t; e2 < nrows * TN; e2 += NTHREADS) {
        const int r = e2 >> 5, c = e2 & 31, j = r >> 1, h = r & 1;
        float v = 0.f;
#pragma unroll
        for (int ww = 0; ww < NWARPS; ww++)
            v += redf[(((ww * 8 + j) * 32 + c) << 1) + h];
        out[(size_t)rowlist[r] * NDIM + n0 + c] = fmaxf(v, 0.f);
    }
}

extern "C" void kernel_launch(void* const* d_in, const int* in_sizes, int n_in,
                              void* d_out, int out_size)
{
    const float* x = nullptr; const int* state = nullptr;
    const float* kern = nullptr; const float* masks = nullptr;
    for (int i = 0; i < n_in; i++) {
        switch (in_sizes[i]) {
            case BS * KDIM:             x = (const float*)d_in[i]; break;
            case BS:                    state = (const int*)d_in[i]; break;
            case KDIM * NDIM:           kern = (const float*)d_in[i]; break;
            case NSTATES * KDIM * NDIM: masks = (const float*)d_in[i]; break;
            default: break;
        }
    }
    float* out = (float*)d_out;

    cudaFuncSetAttribute(masked_dense_kernel,
                         cudaFuncAttributeMaxDynamicSharedMemorySize, SMEM_BYTES);

    build_entries_kernel<<<1, NTHREADS>>>(state);
    dim3 grid(NDIM / TN, MAXE);          // (32, 36)
    masked_dense_kernel<<<grid, NTHREADS, SMEM_BYTES>>>(x, kern, masks, out);
}